// round 13
// baseline (speedup 1.0000x reference)
#include <cuda_runtime.h>
#include <cuda_bf16.h>
#include <cstdint>

#define F_OUT 2080
#define FP2   2176                // 17*128
#define DD    1024
#define NB    16
#define KEFF  6144                // 6 bf16 slots per original k
#define BK    64
#define NIT   96                  // KEFF/BK
#define STGB  49152               // per stage: A 16KB + Bre 16KB + Bim 16KB
#define SMEM_BYTES (3 * STGB)     // 144KB, 1 CTA/SM (512 threads)

typedef __nv_bfloat16 bf16;

__device__ bf16 g_Apk [(size_t)FP2 * KEFF];
__device__ bf16 g_A2re[(size_t)FP2 * KEFF];
__device__ bf16 g_A2im[(size_t)FP2 * KEFF];
__device__ bf16 g_Bre [(size_t)NB * DD * KEFF];
__device__ bf16 g_Bim [(size_t)NB * DD * KEFF];
__device__ bf16 g_Tpk [(size_t)NB * FP2 * KEFF];

// ---------------- helpers ----------------------------------------------------
__device__ __forceinline__ uint32_t s2u(const void* p) {
    uint32_t a; asm("{ .reg .u64 t; cvta.to.shared.u64 t, %1; cvt.u32.u64 %0, t; }"
                    : "=r"(a) : "l"(p)); return a;
}
__device__ __forceinline__ void cpa(uint32_t sa, const void* g) {
    asm volatile("cp.async.cg.shared.global [%0], [%1], 16;" :: "r"(sa), "l"(g));
}
#define CP_COMMIT() asm volatile("cp.async.commit_group;" ::: "memory")

__device__ __forceinline__ void ldsm4(uint32_t (&r)[4], uint32_t a) {
    asm volatile("ldmatrix.sync.aligned.m8n8.x4.shared.b16 {%0,%1,%2,%3}, [%4];"
        : "=r"(r[0]), "=r"(r[1]), "=r"(r[2]), "=r"(r[3]) : "r"(a));
}
__device__ __forceinline__ void mma16816(float (&d)[4], const uint32_t (&a)[4],
                                         uint32_t b0, uint32_t b1) {
    asm volatile("mma.sync.aligned.m16n8k16.row.col.f32.bf16.bf16.f32 "
        "{%0,%1,%2,%3},{%4,%5,%6,%7},{%8,%9},{%0,%1,%2,%3};"
        : "+f"(d[0]), "+f"(d[1]), "+f"(d[2]), "+f"(d[3])
        : "r"(a[0]), "r"(a[1]), "r"(a[2]), "r"(a[3]), "r"(b0), "r"(b1));
}
__device__ __forceinline__ void splt(float x, float& h, float& l) {
    h = __bfloat162float(__float2bfloat16_rn(x)); l = x - h;
}
__device__ __forceinline__ uint32_t pk2(float a, float b) {
    unsigned short ua = __bfloat16_as_ushort(__float2bfloat16_rn(a));
    unsigned short ub = __bfloat16_as_ushort(__float2bfloat16_rn(b));
    return (uint32_t)ua | ((uint32_t)ub << 16);
}

// ---------------- pack A (stage1 A-plane + stage2 B-planes) ------------------
__global__ void pack_amps(const float* __restrict__ U_re, const float* __restrict__ U_im) {
    int f = blockIdx.x, t = threadIdx.x;
    if (f >= F_OUT) {
        uint4 z = make_uint4(0, 0, 0, 0);
        uint4* a = (uint4*)(g_Apk  + (size_t)f * KEFF);
        uint4* r = (uint4*)(g_A2re + (size_t)f * KEFF);
        uint4* m = (uint4*)(g_A2im + (size_t)f * KEFF);
        for (int i = t; i < KEFF / 8; i += 256) { a[i] = z; r[i] = z; m[i] = z; }
        return;
    }
    int j = 0, rem = f;
    while (rem >= 64 - j) { rem -= 64 - j; ++j; }
    int k = j + rem;
    __shared__ float su[4][64];
    if (t < 64) { su[0][t] = U_re[j*64+t]; su[1][t] = U_im[j*64+t];
                  su[2][t] = U_re[k*64+t]; su[3][t] = U_im[k*64+t]; }
    __syncthreads();
    float sc = (j == k) ? 0.7071067811865476f : 1.0f;
    for (int i = t; i < DD; i += 256) {
        int x = i >> 5, y = i & 31;
        float ar = su[0][x], ai = su[1][x], br = su[2][32+y], bi = su[3][32+y];
        float cr = su[2][x], ci = su[3][x], dr = su[0][32+y], di = su[1][32+y];
        float re = sc * (ar*br - ai*bi + cr*dr - ci*di);
        float im = sc * (ar*bi + ai*br + cr*di + ci*dr);
        float rh, rl, ih, il; splt(re, rh, rl); splt(im, ih, il);
        size_t e = (size_t)f * KEFF + 6 * i;
        uint32_t* pA = (uint32_t*)(g_Apk  + e);
        uint32_t* pR = (uint32_t*)(g_A2re + e);
        uint32_t* pI = (uint32_t*)(g_A2im + e);
        pA[0]=pk2(rh,rl);   pA[1]=pk2(rh,ih);  pA[2]=pk2(il,ih);
        pR[0]=pk2(rh,rh);   pR[1]=pk2(rl,ih);  pR[2]=pk2(ih,il);
        pI[0]=pk2(-ih,-ih); pI[1]=pk2(-il,rh); pI[2]=pk2(rh,rl);
    }
}

// ---------------- pack B (stage1 B-planes from rho upper triangle) -----------
__global__ void pack_B(const float* __restrict__ rr, const float* __restrict__ ri) {
    int n = blockIdx.x, b = blockIdx.y, t = threadIdx.x;
    const size_t rb = (size_t)b * DD * DD;
    for (int k = t; k < DD; k += 256) {
        float Br, Bi;
        if (k < n)      { Br = rr[rb + (size_t)k*DD + n]; Bi = ri[rb + (size_t)k*DD + n]; }
        else if (k > n) { Br = rr[rb + (size_t)n*DD + k]; Bi = -ri[rb + (size_t)n*DD + k]; }
        else            { Br = rr[rb + (size_t)n*DD + n]; Bi = 0.f; }
        float rh, rl, ih, il; splt(Br, rh, rl); splt(Bi, ih, il);
        size_t e = ((size_t)b*DD + n) * KEFF + 6*k;
        uint32_t* pR = (uint32_t*)(g_Bre + e);
        uint32_t* pI = (uint32_t*)(g_Bim + e);
        pR[0]=pk2(rh,rh); pR[1]=pk2(rl,-ih); pR[2]=pk2(-ih,-il);
        pI[0]=pk2(ih,ih); pI[1]=pk2(il,rh);  pI[2]=pk2(rh,rl);
    }
}

// ---------------- warp-MMA GEMM (both stages) --------------------------------
// CTA: M=128 x N=128 complex, 512 threads = 16 warps = plane(2) x mh(2) x nh(4),
// warp tile 64x32 real. 3-stage cp.async pipeline + frag double-buffering.
template <int STAGE>
__global__ void __launch_bounds__(512, 1) gemm_mma(float* __restrict__ out) {
    const int tid = threadIdx.x, lane = tid & 31, wid = tid >> 5;
    const int bx = blockIdx.x, by = blockIdx.y, bz = blockIdx.z;
    if (STAGE == 2 && bx < by) return;       // Hermitian: tile fully below diag
    extern __shared__ __align__(128) char smem[];
    const uint32_t sb = s2u(smem);

    const bf16 *Ag, *Brg, *Big;
    if (STAGE == 1) {
        Ag  = g_Apk + (size_t)(by * 128) * KEFF;
        Brg = g_Bre + ((size_t)bz * DD + bx * 128) * KEFF;
        Big = g_Bim + ((size_t)bz * DD + bx * 128) * KEFF;
    } else {
        Ag  = g_Tpk + ((size_t)bz * FP2 + by * 128) * KEFF;
        Brg = g_A2re + (size_t)(bx * 128) * KEFF;
        Big = g_A2im + (size_t)(bx * 128) * KEFF;
    }
    const int plane = wid & 1, mh = (wid >> 1) & 1, nh = wid >> 2;   // nh: 0..3

    float acc[4][4][4];
#pragma unroll
    for (int a = 0; a < 4; ++a)
#pragma unroll
        for (int b2 = 0; b2 < 4; ++b2)
#pragma unroll
            for (int c2 = 0; c2 < 4; ++c2) acc[a][b2][c2] = 0.f;

    // loader: r = row (0..127), q*2 lines of 16B; 6 cp.async per thread/stage
    const int lr = tid >> 2, lq = (tid & 3) * 2;

    auto load_stage = [&](int c, int buf) {
        uint32_t bb = sb + buf * STGB;
        const bf16* as = Ag  + (size_t)lr * KEFF + c * BK;
        const bf16* rs = Brg + (size_t)lr * KEFF + c * BK;
        const bf16* is = Big + (size_t)lr * KEFF + c * BK;
#pragma unroll
        for (int i = 0; i < 2; ++i) {
            int ch = lq + i;
            uint32_t sw = lr * 128 + ((ch ^ (lr & 7)) << 4);
            cpa(bb + sw,         as + ch * 8);
            cpa(bb + 16384 + sw, rs + ch * 8);
            cpa(bb + 32768 + sw, is + ch * 8);
        }
    };

    load_stage(0, 0); CP_COMMIT();
    load_stage(1, 1); CP_COMMIT();

    uint32_t af[2][4][4], bfr[2][2][4];

    int buf = 0;
    for (int c = 0; c < NIT; ++c) {
        if (c + 1 < NIT) asm volatile("cp.async.wait_group 1;" ::: "memory");
        else             asm volatile("cp.async.wait_group 0;" ::: "memory");
        __syncthreads();
        if (c + 2 < NIT) {
            int nb = buf + 2; if (nb >= 3) nb -= 3;
            load_stage(c + 2, nb);
            CP_COMMIT();
        }
        const uint32_t bb = sb + buf * STGB;
        const uint32_t sA = bb;
        const uint32_t sB = bb + 16384 + plane * 16384;

        // prefetch ks=0 fragments
#pragma unroll
        for (int mi = 0; mi < 4; ++mi) {
            int m = mh * 64 + mi * 16 + (lane & 15);
            int ch = (lane >> 4);
            ldsm4(af[0][mi], sA + m * 128 + ((ch ^ (m & 7)) << 4));
        }
#pragma unroll
        for (int nj = 0; nj < 2; ++nj) {
            int n = nh * 32 + nj * 16 + (lane & 7) + ((lane >> 4) << 3);
            int ch = ((lane >> 3) & 1);
            ldsm4(bfr[0][nj], sB + n * 128 + ((ch ^ (n & 7)) << 4));
        }
#pragma unroll
        for (int ks = 0; ks < 4; ++ks) {
            const int cur = ks & 1, nxt = cur ^ 1;
            if (ks < 3) {
#pragma unroll
                for (int mi = 0; mi < 4; ++mi) {
                    int m = mh * 64 + mi * 16 + (lane & 15);
                    int ch = (ks + 1) * 2 + (lane >> 4);
                    ldsm4(af[nxt][mi], sA + m * 128 + ((ch ^ (m & 7)) << 4));
                }
#pragma unroll
                for (int nj = 0; nj < 2; ++nj) {
                    int n = nh * 32 + nj * 16 + (lane & 7) + ((lane >> 4) << 3);
                    int ch = (ks + 1) * 2 + ((lane >> 3) & 1);
                    ldsm4(bfr[nxt][nj], sB + n * 128 + ((ch ^ (n & 7)) << 4));
                }
            }
#pragma unroll
            for (int mi = 0; mi < 4; ++mi)
#pragma unroll
                for (int ni = 0; ni < 4; ++ni)
                    mma16816(acc[mi][ni], af[cur][mi],
                             bfr[cur][ni >> 1][(ni & 1) * 2],
                             bfr[cur][ni >> 1][(ni & 1) * 2 + 1]);
        }
        if (++buf == 3) buf = 0;
    }

    // ---- epilogue: stage planes in smem (re @0, im @64KB), combine, write ----
    __syncthreads();
    float* stR = (float*)smem;
    float* stI = (float*)(smem + 65536);
    float* st = plane ? stI : stR;
#pragma unroll
    for (int mi = 0; mi < 4; ++mi)
#pragma unroll
        for (int ni = 0; ni < 4; ++ni) {
            int r0 = mh * 64 + mi * 16 + (lane >> 2);
            int col = nh * 32 + ni * 8 + (lane & 3) * 2;
            *(float2*)&st[r0 * 128 + col]       = make_float2(acc[mi][ni][0], acc[mi][ni][1]);
            *(float2*)&st[(r0 + 8) * 128 + col] = make_float2(acc[mi][ni][2], acc[mi][ni][3]);
        }
    __syncthreads();

    const int row = tid >> 2;
    const int c0 = (tid & 3) * 32;
    if (STAGE == 1) {
        int f = by * 128 + row;
        char* Trow = (char*)(g_Tpk + ((size_t)bz * FP2 + f) * KEFF);
#pragma unroll 2
        for (int m = 0; m < 8; ++m) {
            uint32_t u[12];
#pragma unroll
            for (int t2 = 0; t2 < 4; ++t2) {
                float re = stR[row * 128 + c0 + m * 4 + t2];
                float im = stI[row * 128 + c0 + m * 4 + t2];
                float rh, rl, ih, il; splt(re, rh, rl); splt(im, ih, il);
                u[t2*3+0] = pk2(rh, rl); u[t2*3+1] = pk2(rh, ih); u[t2*3+2] = pk2(il, ih);
            }
            int n0 = bx * 128 + c0 + m * 4;
            uint4* p = (uint4*)(Trow + (size_t)12 * n0);
            p[0] = make_uint4(u[0], u[1], u[2],  u[3]);
            p[1] = make_uint4(u[4], u[5], u[6],  u[7]);
            p[2] = make_uint4(u[8], u[9], u[10], u[11]);
        }
    } else {
        int f = by * 128 + row;
        if (f < F_OUT) {
            float2* o = (float2*)out + (size_t)bz * F_OUT * F_OUT;
#pragma unroll 4
            for (int j2 = 0; j2 < 32; ++j2) {
                int g = bx * 128 + c0 + j2;
                if (g < F_OUT && f <= g) {
                    float re = stR[row * 128 + c0 + j2];
                    float im = stI[row * 128 + c0 + j2];
                    if (f == g) im = 0.f;
                    o[(size_t)f * F_OUT + g] = make_float2(re, im);
                    if (f < g) o[(size_t)g * F_OUT + f] = make_float2(re, -im);
                }
            }
        }
    }
}

// ---------------- launch -----------------------------------------------------
extern "C" void kernel_launch(void* const* d_in, const int* in_sizes, int n_in,
                              void* d_out, int out_size) {
    const float* rho_re = (const float*)d_in[0];
    const float* rho_im = (const float*)d_in[1];
    const float* U_re   = (const float*)d_in[2];
    const float* U_im   = (const float*)d_in[3];

    cudaFuncSetAttribute(gemm_mma<1>, cudaFuncAttributeMaxDynamicSharedMemorySize, SMEM_BYTES);
    cudaFuncSetAttribute(gemm_mma<2>, cudaFuncAttributeMaxDynamicSharedMemorySize, SMEM_BYTES);

    pack_amps<<<FP2, 256>>>(U_re, U_im);
    pack_B<<<dim3(DD, NB), 256>>>(rho_re, rho_im);
    gemm_mma<1><<<dim3(8, 17, NB), 512, SMEM_BYTES>>>(nullptr);
    gemm_mma<2><<<dim3(17, 17, NB), 512, SMEM_BYTES>>>((float*)d_out);
}

// round 14
// speedup vs baseline: 2.4378x; 2.4378x over previous
#include <cuda_runtime.h>
#include <cstdint>

#define DD 1024
#define NB 16
#define NF 2080

__device__ float2 g_H [(size_t)NB * DD * DD];          // Hermitianized rho
__device__ float2 g_H2[(size_t)NB * 64 * 32 * DD];     // [b][a][x][n]
__device__ float2 g_G [(size_t)NB * 64 * 64 * DD];     // [b][c][a][n]
__device__ int    g_pairs[NF];

__global__ void pairs_init() {
    int g = blockIdx.x * 256 + threadIdx.x;
    if (g < NF) {
        int j = 0, rem = g;
        while (rem >= 64 - j) { rem -= 64 - j; ++j; }
        g_pairs[g] = (j << 8) | (j + rem);
    }
}

// ---- Hermitianize rho upper triangle into g_H (float2) ----------------------
__global__ void pack_H(const float* __restrict__ rr, const float* __restrict__ ri) {
    int ti = blockIdx.x, tj = blockIdx.y, b = blockIdx.z;
    if (tj < ti) return;
    __shared__ float sr[32][33], si[32][33];
    int cx = threadIdx.x, ry = threadIdx.y;
    const size_t base = (size_t)b * DD * DD;
    int r = ti * 32 + ry, c = tj * 32 + cx;
    sr[ry][cx] = rr[base + (size_t)r * DD + c];
    si[ry][cx] = ri[base + (size_t)r * DD + c];
    __syncthreads();
    float2* H = g_H + base;
    if (ti == tj) {
        float2 v;
        if (ry < cx)      v = make_float2(sr[ry][cx], si[ry][cx]);
        else if (ry > cx) v = make_float2(sr[cx][ry], -si[cx][ry]);
        else              v = make_float2(sr[ry][cx], 0.f);
        H[(size_t)r * DD + c] = v;
    } else {
        H[(size_t)r * DD + c] = make_float2(sr[ry][cx], si[ry][cx]);
        int r2 = tj * 32 + ry, c2 = ti * 32 + cx;
        H[(size_t)r2 * DD + c2] = make_float2(sr[cx][ry], -si[cx][ry]);
    }
}

// ---- small-K GEMM: OUT[64,128] = M(64x32) * IN(32x128) ----------------------
// MODE1: IN = H rows (x,y) for fixed x=sl, M=Uq -> H2[b][a][sl][n]
// MODE2: IN = H2[b][sl][x][n],              M=Up -> G[b][c][sl][n]
template <int MODE>
__global__ void __launch_bounds__(256) s1_gemm(const float* __restrict__ U_re,
                                               const float* __restrict__ U_im) {
    const int nt = blockIdx.x, sl = blockIdx.y, b = blockIdx.z;
    __shared__ float2 sM[64][32];
    __shared__ float2 sIn[32][128];
    const int tid = threadIdx.x;
    const int mcol = (MODE == 1) ? 32 : 0;
#pragma unroll
    for (int i = 0; i < 8; ++i) {
        int idx = tid * 8 + i;
        int a = idx >> 5, kk = idx & 31;
        sM[a][kk] = make_float2(U_re[a * 64 + mcol + kk], U_im[a * 64 + mcol + kk]);
    }
    const float2* inb; float2* outb; size_t outstr;
    if (MODE == 1) {
        inb  = g_H  + ((size_t)b * DD + sl * 32) * DD + nt * 128;
        outb = g_H2 + ((size_t)(b * 64) * 32 + sl) * DD + nt * 128;
        outstr = (size_t)32 * DD;
    } else {
        inb  = g_H2 + ((size_t)(b * 64 + sl)) * 32 * DD + nt * 128;
        outb = g_G  + ((size_t)(b * 64) * 64 + sl) * DD + nt * 128;
        outstr = (size_t)64 * DD;
    }
    {
        int row = tid >> 3, q = tid & 7;
        const float4* src = (const float4*)(inb + (size_t)row * DD);
        float4* dst = (float4*)&sIn[row][0];
#pragma unroll
        for (int i = 0; i < 8; ++i) dst[q + i * 8] = src[q + i * 8];
    }
    __syncthreads();
    const int a0 = (tid >> 5) * 8, c0 = tid & 31;
    float2 acc[8][4];
#pragma unroll
    for (int i = 0; i < 8; ++i)
#pragma unroll
        for (int j = 0; j < 4; ++j) acc[i][j] = make_float2(0.f, 0.f);
#pragma unroll 4
    for (int kk = 0; kk < 32; ++kk) {
        float2 m[8], h[4];
#pragma unroll
        for (int i = 0; i < 8; ++i) m[i] = sM[a0 + i][kk];
#pragma unroll
        for (int j = 0; j < 4; ++j) h[j] = sIn[kk][c0 + 32 * j];
#pragma unroll
        for (int i = 0; i < 8; ++i)
#pragma unroll
            for (int j = 0; j < 4; ++j) {
                acc[i][j].x = fmaf(m[i].x, h[j].x, fmaf(-m[i].y, h[j].y, acc[i][j].x));
                acc[i][j].y = fmaf(m[i].x, h[j].y, fmaf( m[i].y, h[j].x, acc[i][j].y));
            }
    }
#pragma unroll
    for (int i = 0; i < 8; ++i)
#pragma unroll
        for (int j = 0; j < 4; ++j)
            outb[(size_t)(a0 + i) * outstr + c0 + 32 * j] = acc[i][j];
}

// ---- fused stage 2: per (b,f): T -> Z -> W -> output row --------------------
#define S2_SMEM (11424 * 8)
__global__ void __launch_bounds__(256) s2_fused(const float* __restrict__ U_re,
                                                const float* __restrict__ U_im,
                                                float2* __restrict__ out) {
    extern __shared__ float2 dsm[];
    float2* sVp = dsm;            // [64][33] conj(U[a][x])
    float2* sVq = dsm + 2112;     // [64][33] conj(U[a][32+y])
    float2* sT  = dsm + 4224;     // [32][33]
    float2* sZ  = dsm + 5280;     // [32][64]
    float2* sW  = dsm + 7328;     // [64][64]
    const int f = blockIdx.x, b = blockIdx.y, tid = threadIdx.x;
    const int pr = g_pairs[f], j = pr >> 8, k = pr & 255;
    const float sf = (j == k) ? 0.7071067811865476f : 1.f;

    for (int i = tid; i < 2048; i += 256) {
        int a = i >> 5, x = i & 31;
        sVp[a * 33 + x] = make_float2(U_re[a * 64 + x],      -U_im[a * 64 + x]);
        sVq[a * 33 + x] = make_float2(U_re[a * 64 + 32 + x], -U_im[a * 64 + 32 + x]);
    }
    const float2* r1 = g_G + (((size_t)b * 64 + j) * 64 + k) * DD;
    const float2* r2 = g_G + (((size_t)b * 64 + k) * 64 + j) * DD;
    for (int n = tid; n < DD; n += 256) {
        float2 u = r1[n], v = r2[n];
        sT[(n >> 5) * 33 + (n & 31)] = make_float2(sf * (u.x + v.x), sf * (u.y + v.y));
    }
    __syncthreads();

    {   // Z[x][b'] = sum_y T[x][y] * Vq[b'][y]
        const int bp = tid & 63, x0 = (tid >> 6) * 8;
        float2 acc[8];
#pragma unroll
        for (int i = 0; i < 8; ++i) acc[i] = make_float2(0.f, 0.f);
#pragma unroll 4
        for (int y = 0; y < 32; ++y) {
            float2 v = sVq[bp * 33 + y];
#pragma unroll
            for (int i = 0; i < 8; ++i) {
                float2 t = sT[(x0 + i) * 33 + y];
                acc[i].x = fmaf(t.x, v.x, fmaf(-t.y, v.y, acc[i].x));
                acc[i].y = fmaf(t.x, v.y, fmaf( t.y, v.x, acc[i].y));
            }
        }
#pragma unroll
        for (int i = 0; i < 8; ++i) sZ[(x0 + i) * 64 + bp] = acc[i];
    }
    __syncthreads();
    {   // W[a'][b'] = sum_x Vp[a'][x] * Z[x][b']
        const int bp = tid & 63, a0 = (tid >> 6) * 16;
        float2 acc[16];
#pragma unroll
        for (int i = 0; i < 16; ++i) acc[i] = make_float2(0.f, 0.f);
#pragma unroll 2
        for (int x = 0; x < 32; ++x) {
            float2 z = sZ[x * 64 + bp];
#pragma unroll
            for (int i = 0; i < 16; ++i) {
                float2 p = sVp[(a0 + i) * 33 + x];
                acc[i].x = fmaf(p.x, z.x, fmaf(-p.y, z.y, acc[i].x));
                acc[i].y = fmaf(p.x, z.y, fmaf( p.y, z.x, acc[i].y));
            }
        }
#pragma unroll
        for (int i = 0; i < 16; ++i) sW[(a0 + i) * 64 + bp] = acc[i];
    }
    __syncthreads();
    float2* row = out + ((size_t)b * NF + f) * NF;
    for (int g = tid; g < NF; g += 256) {
        int p2 = g_pairs[g], j2 = p2 >> 8, k2 = p2 & 255;
        float sg = (j2 == k2) ? 0.7071067811865476f : 1.f;
        float2 w1 = sW[j2 * 64 + k2], w2 = sW[k2 * 64 + j2];
        float2 v = make_float2(sg * (w1.x + w2.x), sg * (w1.y + w2.y));
        if (g == f) v.y = 0.f;
        row[g] = v;
    }
}

// ---- launch ------------------------------------------------------------------
extern "C" void kernel_launch(void* const* d_in, const int* in_sizes, int n_in,
                              void* d_out, int out_size) {
    const float* rho_re = (const float*)d_in[0];
    const float* rho_im = (const float*)d_in[1];
    const float* U_re   = (const float*)d_in[2];
    const float* U_im   = (const float*)d_in[3];

    cudaFuncSetAttribute(s2_fused, cudaFuncAttributeMaxDynamicSharedMemorySize, S2_SMEM);

    pairs_init<<<9, 256>>>();
    pack_H<<<dim3(32, 32, NB), dim3(32, 32)>>>(rho_re, rho_im);
    s1_gemm<1><<<dim3(8, 32, NB), 256>>>(U_re, U_im);
    s1_gemm<2><<<dim3(8, 64, NB), 256>>>(U_re, U_im);
    s2_fused<<<dim3(NF, NB), 256, S2_SMEM>>>(U_re, U_im, (float2*)d_out);
}